// round 15
// baseline (speedup 1.0000x reference)
#include <cuda_runtime.h>
#include <cuda_fp16.h>
#include <cstdint>

// ---------------------------------------------------------------- shapes
#define M_TOTAL 16384
#define D_DIM   4096
#define RANK    819
#define KPAD    832          // gemm2 K (rank padded to 64)
#define NPAD1   896          // Y columns padded (cols >=832 unused)
#define NACT1   832          // active N columns in gemm1

// ---------------------------------------------------------------- scratch
__device__ uint32_t g_Xh[(size_t)M_TOTAL * (D_DIM / 2)];   // x, [m][k-pair]
__device__ uint32_t g_Yh[(size_t)M_TOTAL * (NPAD1 / 2)];   // Y, [m][n-pair]
__device__ uint32_t g_B1[(size_t)(D_DIM / 2) * NPAD1];     // (U*S), [k-pair][n]
__device__ uint32_t g_B2[(size_t)(KPAD / 2) * D_DIM];      // V,     [k-pair][n]

// ---------------------------------------------------------------- helpers
static __device__ __forceinline__ uint32_t s2u(const void* p) {
    uint32_t a;
    asm("{ .reg .u64 t; cvta.to.shared.u64 t, %1; cvt.u32.u64 %0, t; }"
        : "=r"(a) : "l"(p));
    return a;
}
static __device__ __forceinline__ uint32_t pkh2(float x, float y) {
    __half2 h = __floats2half2_rn(x, y);
    return *reinterpret_cast<uint32_t*>(&h);
}
static __device__ __forceinline__ void cp16(uint32_t dst, const void* src) {
    asm volatile("cp.async.cg.shared.global [%0], [%1], 16;"
                 :: "r"(dst), "l"(src) : "memory");
}
#define CP_COMMIT() asm volatile("cp.async.commit_group;" ::: "memory")
#define CP_WAIT1()  asm volatile("cp.async.wait_group 1;" ::: "memory")

static __device__ __forceinline__ void mma16(float c[4],
                                             uint32_t a0, uint32_t a1,
                                             uint32_t a2, uint32_t a3,
                                             uint32_t b0, uint32_t b1) {
    asm volatile(
        "mma.sync.aligned.m16n8k16.row.col.f32.f16.f16.f32 "
        "{%0,%1,%2,%3}, {%4,%5,%6,%7}, {%8,%9}, {%0,%1,%2,%3};"
        : "+f"(c[0]), "+f"(c[1]), "+f"(c[2]), "+f"(c[3])
        : "r"(a0), "r"(a1), "r"(a2), "r"(a3), "r"(b0), "r"(b1));
}

// ---------------------------------------------------------------- merged prep
#define NX4 ((size_t)M_TOTAL * D_DIM / 4)
#define NB1 ((size_t)(D_DIM / 2) * NPAD1)
#define NB2 ((size_t)(KPAD / 2) * D_DIM)
#define NPREP (NX4 + NB1 + NB2)

__global__ void prep_all(const float4* __restrict__ X, uint2* __restrict__ Xh,
                         const float* __restrict__ U, const float* __restrict__ S,
                         uint32_t* __restrict__ B1,
                         const float* __restrict__ V, uint32_t* __restrict__ B2) {
    const size_t id = (size_t)blockIdx.x * blockDim.x + threadIdx.x;
    if (id < NX4) {
        float4 v = X[id];
        uint2 o;
        o.x = pkh2(v.x, v.y);
        o.y = pkh2(v.z, v.w);
        Xh[id] = o;
    } else if (id < NX4 + NB1) {
        const size_t i = id - NX4;
        const int n = (int)(i % NPAD1);
        const int kp = (int)(i / NPAD1);
        float v0 = 0.0f, v1 = 0.0f;
        if (n < RANK) {
            const float s = S[n];
            v0 = U[(size_t)(2 * kp) * RANK + n] * s;
            v1 = U[(size_t)(2 * kp + 1) * RANK + n] * s;
        }
        B1[i] = pkh2(v0, v1);
    } else {
        const size_t i = id - NX4 - NB1;
        const int n = (int)(i & (D_DIM - 1));
        const int kp = (int)(i >> 12);
        const int k0 = 2 * kp;
        float v0 = 0.0f, v1 = 0.0f;
        if (k0 < RANK)     v0 = V[(size_t)k0 * D_DIM + n];
        if (k0 + 1 < RANK) v1 = V[(size_t)(k0 + 1) * D_DIM + n];
        B2[i] = pkh2(v0, v1);
    }
}

// ---------------------------------------------------------------- tiles
// Both GEMMs: CTA 128x128, 4 warps (2M x 2N), warp 64x64, 128 thr, occ 2.
#define BKW 32
#define STAGES 3
#define NT 128
#define ASTRIDE 36
#define BSTRIDE 136
#define AW (128 * ASTRIDE)                // 4608 words
#define BW (BKW * BSTRIDE)                // 4352 words
#define SW (AW + BW)                      // 8960 words
#define SMEM_B (STAGES * SW * 4)          // 107520 B

// ================================================================= GEMM 1
// Yh[16384][896] = Xh @ B1.  grid (7,128), occ 2.  (R12-proven, unchanged.)
__global__ __launch_bounds__(NT, 2)
void gemm1(const uint32_t* __restrict__ Ag, const uint32_t* __restrict__ Bg,
           uint32_t* __restrict__ Yw) {
    extern __shared__ __align__(128) uint32_t sm[];
    const int tid = threadIdx.x;
    const int lane = tid & 31, wid = tid >> 5;
    const int gid = lane >> 2, tg = lane & 3;
    const int warpM = wid & 1, warpN = wid >> 1;   // MFAST: warpN over SMSPs
    const int bm = blockIdx.y * 128, bn = blockIdx.x * 128;
    const uint32_t smu = s2u(sm);
    const bool active = (bn + warpN * 64) < NACT1;
    constexpr int KT = D_DIM / 64;                 // 64

    float c[4][8][4];
    #pragma unroll
    for (int i = 0; i < 4; i++)
        #pragma unroll
        for (int j = 0; j < 8; j++)
            #pragma unroll
            for (int v = 0; v < 4; v++) c[i][j][v] = 0.0f;

    #define LOADST1(slot, kw0)                                                 \
    do {                                                                       \
        const uint32_t base = smu + (slot) * (SW * 4);                         \
        _Pragma("unroll")                                                      \
        for (int ii = 0; ii < 16; ii++) {                                      \
            const int id = tid + NT * ii;                                      \
            if (id < 1024) {                                                   \
                const int row = id >> 3, cc = id & 7;                          \
                cp16(base + (row * ASTRIDE + cc * 4) * 4,                      \
                     Ag + (size_t)(bm + row) * (D_DIM / 2) + (kw0) + cc * 4);  \
            } else {                                                           \
                const int id2 = id - 1024;                                     \
                const int row = id2 >> 5, cc = id2 & 31;                       \
                cp16(base + (AW + row * BSTRIDE + cc * 4) * 4,                 \
                     Bg + (size_t)((kw0) + row) * NPAD1 + bn + cc * 4);        \
            }                                                                  \
        }                                                                      \
    } while (0)

    LOADST1(0, 0);    CP_COMMIT();
    LOADST1(1, BKW);  CP_COMMIT();

    int slot = 0;
    for (int t = 0; t < KT; t++) {
        CP_WAIT1();
        __syncthreads();
        if (t + 2 < KT) {
            const int ns = (slot + 2 >= STAGES) ? slot + 2 - STAGES : slot + 2;
            LOADST1(ns, (t + 2) * BKW);
        }
        CP_COMMIT();

        if (active) {
            const uint32_t* As = sm + slot * SW;
            const uint32_t* Bs = As + AW;

            uint32_t af[2][4][4];
            #pragma unroll
            for (int i = 0; i < 4; i++) {
                const int r0 = warpM * 64 + i * 16 + gid;
                af[0][i][0] = As[r0 * ASTRIDE + tg];
                af[0][i][1] = As[(r0 + 8) * ASTRIDE + tg];
                af[0][i][2] = As[r0 * ASTRIDE + tg + 4];
                af[0][i][3] = As[(r0 + 8) * ASTRIDE + tg + 4];
            }
            #pragma unroll
            for (int ks = 0; ks < 4; ks++) {
                const int cur = ks & 1, nxt = cur ^ 1;
                if (ks < 3) {
                    const int cbw = (ks + 1) * 8;
                    #pragma unroll
                    for (int i = 0; i < 4; i++) {
                        const int r0 = warpM * 64 + i * 16 + gid;
                        af[nxt][i][0] = As[r0 * ASTRIDE + cbw + tg];
                        af[nxt][i][1] = As[(r0 + 8) * ASTRIDE + cbw + tg];
                        af[nxt][i][2] = As[r0 * ASTRIDE + cbw + tg + 4];
                        af[nxt][i][3] = As[(r0 + 8) * ASTRIDE + cbw + tg + 4];
                    }
                }
                const int kp0 = ks * 8;
                #pragma unroll
                for (int j = 0; j < 8; j++) {
                    const int col = warpN * 64 + j * 8 + gid;
                    const uint32_t b0 = Bs[(kp0 + tg) * BSTRIDE + col];
                    const uint32_t b1 = Bs[(kp0 + 4 + tg) * BSTRIDE + col];
                    #pragma unroll
                    for (int i = 0; i < 4; i++)
                        mma16(c[i][j], af[cur][i][0], af[cur][i][1],
                              af[cur][i][2], af[cur][i][3], b0, b1);
                }
            }
        }
        slot = (slot + 1 >= STAGES) ? 0 : slot + 1;
    }
    #undef LOADST1

    if (!active) return;
    #pragma unroll
    for (int i = 0; i < 4; i++) {
        const int r0 = bm + warpM * 64 + i * 16 + gid;
        #pragma unroll
        for (int j = 0; j < 8; j++) {
            const int n0 = bn + warpN * 64 + j * 8 + tg * 2;
            Yw[(size_t)r0 * (NPAD1 / 2) + (n0 >> 1)]       = pkh2(c[i][j][0], c[i][j][1]);
            Yw[(size_t)(r0 + 8) * (NPAD1 / 2) + (n0 >> 1)] = pkh2(c[i][j][2], c[i][j][3]);
        }
    }
}

// ================================================================= GEMM 2
// Out = Yh[:, :832] @ B2 + alpha * Xh.  Each CTA: TWO m-tiles (bm0, bm0+128)
// at the same bn, one continuous 26-iteration pipeline. grid (32, 64), occ 2.
#define G2_KT 13

__global__ __launch_bounds__(NT, 2)
void gemm2(const uint32_t* __restrict__ Ag, const uint32_t* __restrict__ Bg,
           const uint32_t* __restrict__ Xh, const float* __restrict__ alphap,
           float* __restrict__ Out) {
    extern __shared__ __align__(128) uint32_t sm[];
    const int tid = threadIdx.x;
    const int lane = tid & 31, wid = tid >> 5;
    const int gid = lane >> 2, tg = lane & 3;
    const int warpM = wid >> 1, warpN = wid & 1;
    const int bm0 = blockIdx.y * 256;
    const int bn = blockIdx.x * 128;
    const uint32_t smu = s2u(sm);
    const float alpha = *alphap;

    float c[4][8][4];
    #pragma unroll
    for (int i = 0; i < 4; i++)
        #pragma unroll
        for (int j = 0; j < 8; j++)
            #pragma unroll
            for (int v = 0; v < 4; v++) c[i][j][v] = 0.0f;

    // tt in [0, 26): kt = tt % 13, m-half = tt / 13
    #define LOADST2(slot, tt)                                                  \
    do {                                                                       \
        const int kt_ = (tt) < G2_KT ? (tt) : (tt) - G2_KT;                    \
        const int bm_ = bm0 + (((tt) < G2_KT) ? 0 : 128);                      \
        const int kw0_ = kt_ * BKW;                                            \
        const uint32_t base = smu + (slot) * (SW * 4);                         \
        _Pragma("unroll")                                                      \
        for (int ii = 0; ii < 16; ii++) {                                      \
            const int id = tid + NT * ii;                                      \
            if (id < 1024) {                                                   \
                const int row = id >> 3, cc = id & 7;                          \
                cp16(base + (row * ASTRIDE + cc * 4) * 4,                      \
                     Ag + (size_t)(bm_ + row) * (NPAD1 / 2) + kw0_ + cc * 4);  \
            } else {                                                           \
                const int id2 = id - 1024;                                     \
                const int row = id2 >> 5, cc = id2 & 31;                       \
                cp16(base + (AW + row * BSTRIDE + cc * 4) * 4,                 \
                     Bg + (size_t)(kw0_ + row) * D_DIM + bn + cc * 4);         \
            }                                                                  \
        }                                                                      \
    } while (0)

    LOADST2(0, 0);  CP_COMMIT();
    LOADST2(1, 1);  CP_COMMIT();

    int slot = 0;
    for (int t = 0; t < 2 * G2_KT; t++) {
        CP_WAIT1();
        __syncthreads();
        if (t + 2 < 2 * G2_KT) {
            const int ns = (slot + 2 >= STAGES) ? slot + 2 - STAGES : slot + 2;
            LOADST2(ns, t + 2);
        }
        CP_COMMIT();

        const uint32_t* As = sm + slot * SW;
        const uint32_t* Bs = As + AW;

        uint32_t af[2][4][4];
        #pragma unroll
        for (int i = 0; i < 4; i++) {
            const int r0 = warpM * 64 + i * 16 + gid;
            af[0][i][0] = As[r0 * ASTRIDE + tg];
            af[0][i][1] = As[(r0 + 8) * ASTRIDE + tg];
            af[0][i][2] = As[r0 * ASTRIDE + tg + 4];
            af[0][i][3] = As[(r0 + 8) * ASTRIDE + tg + 4];
        }
        #pragma unroll
        for (int ks = 0; ks < 4; ks++) {
            const int cur = ks & 1, nxt = cur ^ 1;
            if (ks < 3) {
                const int cbw = (ks + 1) * 8;
                #pragma unroll
                for (int i = 0; i < 4; i++) {
                    const int r0 = warpM * 64 + i * 16 + gid;
                    af[nxt][i][0] = As[r0 * ASTRIDE + cbw + tg];
                    af[nxt][i][1] = As[(r0 + 8) * ASTRIDE + cbw + tg];
                    af[nxt][i][2] = As[r0 * ASTRIDE + cbw + tg + 4];
                    af[nxt][i][3] = As[(r0 + 8) * ASTRIDE + cbw + tg + 4];
                }
            }
            const int kp0 = ks * 8;
            #pragma unroll
            for (int j = 0; j < 8; j++) {
                const int col = warpN * 64 + j * 8 + gid;
                const uint32_t b0 = Bs[(kp0 + tg) * BSTRIDE + col];
                const uint32_t b1 = Bs[(kp0 + 4 + tg) * BSTRIDE + col];
                #pragma unroll
                for (int i = 0; i < 4; i++)
                    mma16(c[i][j], af[cur][i][0], af[cur][i][1],
                          af[cur][i][2], af[cur][i][3], b0, b1);
            }
        }
        slot = (slot + 1 >= STAGES) ? 0 : slot + 1;

        // end of an m-half: epilogue + accumulator reset (pipeline continues)
        if (t == G2_KT - 1 || t == 2 * G2_KT - 1) {
            const int bmE = bm0 + ((t == G2_KT - 1) ? 0 : 128);
            #pragma unroll
            for (int i = 0; i < 4; i++) {
                const int r0 = bmE + warpM * 64 + i * 16 + gid;
                #pragma unroll
                for (int j = 0; j < 8; j++) {
                    const int n0 = bn + warpN * 64 + j * 8 + tg * 2;
                    #pragma unroll
                    for (int h = 0; h < 2; h++) {
                        const size_t off = (size_t)(r0 + 8 * h) * D_DIM + n0;
                        const uint32_t xw =
                            Xh[(size_t)(r0 + 8 * h) * (D_DIM / 2) + (n0 >> 1)];
                        const float2 xv =
                            __half22float2(*reinterpret_cast<const __half2*>(&xw));
                        float2 ov;
                        ov.x = fmaf(alpha, xv.x, c[i][j][2 * h + 0]);
                        ov.y = fmaf(alpha, xv.y, c[i][j][2 * h + 1]);
                        *reinterpret_cast<float2*>(Out + off) = ov;
                        c[i][j][2 * h + 0] = 0.0f;
                        c[i][j][2 * h + 1] = 0.0f;
                    }
                }
            }
        }
    }
    #undef LOADST2
}

// ---------------------------------------------------------------- launch
extern "C" void kernel_launch(void* const* d_in, const int* in_sizes, int n_in,
                              void* d_out, int out_size) {
    const float* x     = (const float*)d_in[0];
    const float* U     = (const float*)d_in[1];
    const float* S     = (const float*)d_in[2];
    const float* V     = (const float*)d_in[3];
    const float* alpha = (const float*)d_in[4];
    float* out = (float*)d_out;

    uint32_t *Xhp, *Yhp, *B1p, *B2p;
    cudaGetSymbolAddress((void**)&Xhp, g_Xh);
    cudaGetSymbolAddress((void**)&Yhp, g_Yh);
    cudaGetSymbolAddress((void**)&B1p, g_B1);
    cudaGetSymbolAddress((void**)&B2p, g_B2);

    cudaFuncSetAttribute(gemm1, cudaFuncAttributeMaxDynamicSharedMemorySize,
                         SMEM_B);
    cudaFuncSetAttribute(gemm2, cudaFuncAttributeMaxDynamicSharedMemorySize,
                         SMEM_B);

    prep_all<<<(unsigned)(NPREP / 256), 256>>>((const float4*)x, (uint2*)Xhp,
                                               U, S, B1p, V, B2p);

    gemm1<<<dim3(NPAD1 / 128, M_TOTAL / 128), NT, SMEM_B>>>(Xhp, B1p, Yhp);
    gemm2<<<dim3(D_DIM / 128, M_TOTAL / 256), NT, SMEM_B>>>(Yhp, B2p, Xhp,
                                                            alpha, out);
}

// round 16
// speedup vs baseline: 1.0486x; 1.0486x over previous
#include <cuda_runtime.h>
#include <cuda_fp16.h>
#include <cstdint>

// ---------------------------------------------------------------- shapes
#define M_TOTAL 16384
#define D_DIM   4096
#define RANK    819
#define KPAD    832          // gemm2 K (rank padded to 64)
#define NPAD1   896          // Y/B1 column stride (cols >=832 unused)

// ---------------------------------------------------------------- scratch
__device__ uint32_t g_Xh[(size_t)M_TOTAL * (D_DIM / 2)];   // x, [m][k-pair]
__device__ uint32_t g_Yh[(size_t)M_TOTAL * (NPAD1 / 2)];   // Y, [m][n-pair]
__device__ uint32_t g_B1[(size_t)(D_DIM / 2) * NPAD1];     // (U*S), [k-pair][n]
__device__ uint32_t g_B2[(size_t)(KPAD / 2) * D_DIM];      // V,     [k-pair][n]

// ---------------------------------------------------------------- helpers
static __device__ __forceinline__ uint32_t s2u(const void* p) {
    uint32_t a;
    asm("{ .reg .u64 t; cvta.to.shared.u64 t, %1; cvt.u32.u64 %0, t; }"
        : "=r"(a) : "l"(p));
    return a;
}
static __device__ __forceinline__ uint32_t pkh2(float x, float y) {
    __half2 h = __floats2half2_rn(x, y);
    return *reinterpret_cast<uint32_t*>(&h);
}
static __device__ __forceinline__ void cp16(uint32_t dst, const void* src) {
    asm volatile("cp.async.cg.shared.global [%0], [%1], 16;"
                 :: "r"(dst), "l"(src) : "memory");
}
#define CP_COMMIT() asm volatile("cp.async.commit_group;" ::: "memory")
#define CP_WAIT1()  asm volatile("cp.async.wait_group 1;" ::: "memory")

static __device__ __forceinline__ void mma16(float c[4],
                                             uint32_t a0, uint32_t a1,
                                             uint32_t a2, uint32_t a3,
                                             uint32_t b0, uint32_t b1) {
    asm volatile(
        "mma.sync.aligned.m16n8k16.row.col.f32.f16.f16.f32 "
        "{%0,%1,%2,%3}, {%4,%5,%6,%7}, {%8,%9}, {%0,%1,%2,%3};"
        : "+f"(c[0]), "+f"(c[1]), "+f"(c[2]), "+f"(c[3])
        : "r"(a0), "r"(a1), "r"(a2), "r"(a3), "r"(b0), "r"(b1));
}

// ---------------------------------------------------------------- merged prep
// X path vectorized: 2 float4 reads -> 1 uint4 (16B) store per thread.
#define NX2 ((size_t)M_TOTAL * D_DIM / 8)                 //  8,388,608
#define NB1 ((size_t)(D_DIM / 2) * NPAD1)                 //  1,835,008
#define NB2 ((size_t)(KPAD / 2) * D_DIM)                  //  1,703,936
#define NPREP (NX2 + NB1 + NB2)                           // 11,927,552

__global__ void prep_all(const float4* __restrict__ X, uint4* __restrict__ Xh4,
                         const float* __restrict__ U, const float* __restrict__ S,
                         uint32_t* __restrict__ B1,
                         const float* __restrict__ V, uint32_t* __restrict__ B2) {
    const size_t id = (size_t)blockIdx.x * blockDim.x + threadIdx.x;
    if (id < NX2) {
        float4 a = X[2 * id];
        float4 b = X[2 * id + 1];
        uint4 o;
        o.x = pkh2(a.x, a.y);
        o.y = pkh2(a.z, a.w);
        o.z = pkh2(b.x, b.y);
        o.w = pkh2(b.z, b.w);
        Xh4[id] = o;
    } else if (id < NX2 + NB1) {
        const size_t i = id - NX2;
        const int n = (int)(i % NPAD1);
        const int kp = (int)(i / NPAD1);
        float v0 = 0.0f, v1 = 0.0f;
        if (n < RANK) {
            const float s = S[n];
            v0 = U[(size_t)(2 * kp) * RANK + n] * s;
            v1 = U[(size_t)(2 * kp + 1) * RANK + n] * s;
        }
        B1[i] = pkh2(v0, v1);
    } else {
        const size_t i = id - NX2 - NB1;
        const int n = (int)(i & (D_DIM - 1));
        const int kp = (int)(i >> 12);
        const int k0 = 2 * kp;
        float v0 = 0.0f, v1 = 0.0f;
        if (k0 < RANK)     v0 = V[(size_t)k0 * D_DIM + n];
        if (k0 + 1 < RANK) v1 = V[(size_t)(k0 + 1) * D_DIM + n];
        B2[i] = pkh2(v0, v1);
    }
}

// ---------------------------------------------------------------- tiles
// Both GEMMs: CTA 128x128, 4 warps (2M x 2N), 128 thr, occ 2, 3 stages.
#define BKW 32
#define STAGES 3
#define NT 128
#define ASTRIDE 36
#define BSTRIDE 136
#define AW (128 * ASTRIDE)                // 4608 words
#define BW (BKW * BSTRIDE)                // 4352 words
#define SW (AW + BW)                      // 8960 words
#define SMEM_B (STAGES * SW * 4)          // 107520 B

// ================================================================= GEMM 1
// Yh[16384][:832] = Xh @ B1.
// Full tiles (bn<768): warp tile 64x64 (JN=8).  Edge tile (bn=768): all 4
// warps on the 64 active cols, warp tile 64x32 (JN=4), half mma + half B
// loads -> ~0.6x CTA duration.  Edge tiles get the HIGHEST bids so the
// quantized last wave is made of short CTAs.
template <int JN>
static __device__ __forceinline__ void gemm1_body(
    int bm, int bn,
    const uint32_t* __restrict__ Ag, const uint32_t* __restrict__ Bg,
    uint32_t* __restrict__ Yw)
{
    constexpr int BC = JN * 4;            // B chunks per k-row (32 or 16)
    constexpr int TC = 1024 + BKW * BC;   // total chunks (2048 or 1536)

    extern __shared__ __align__(128) uint32_t sm[];
    const int tid = threadIdx.x;
    const int lane = tid & 31, wid = tid >> 5;
    const int gid = lane >> 2, tg = lane & 3;
    const int warpM = wid >> 1, warpN = wid & 1;
    const uint32_t smu = s2u(sm);
    constexpr int KT = D_DIM / 64;        // 64

    float c[4][JN][4];
    #pragma unroll
    for (int i = 0; i < 4; i++)
        #pragma unroll
        for (int j = 0; j < JN; j++)
            #pragma unroll
            for (int v = 0; v < 4; v++) c[i][j][v] = 0.0f;

    #define LOADST1(slot, kw0)                                                 \
    do {                                                                       \
        const uint32_t base = smu + (slot) * (SW * 4);                         \
        _Pragma("unroll")                                                      \
        for (int ii = 0; ii < TC / NT; ii++) {                                 \
            const int id = tid + NT * ii;                                      \
            if (id < 1024) {                                                   \
                const int row = id >> 3, cc = id & 7;                          \
                cp16(base + (row * ASTRIDE + cc * 4) * 4,                      \
                     Ag + (size_t)(bm + row) * (D_DIM / 2) + (kw0) + cc * 4);  \
            } else {                                                           \
                const int id2 = id - 1024;                                     \
                const int row = id2 / BC, cc = id2 % BC;                       \
                cp16(base + (AW + row * BSTRIDE + cc * 4) * 4,                 \
                     Bg + (size_t)((kw0) + row) * NPAD1 + bn + cc * 4);        \
            }                                                                  \
        }                                                                      \
    } while (0)

    LOADST1(0, 0);    CP_COMMIT();
    LOADST1(1, BKW);  CP_COMMIT();

    int slot = 0;
    for (int t = 0; t < KT; t++) {
        CP_WAIT1();
        __syncthreads();
        if (t + 2 < KT) {
            const int ns = (slot + 2 >= STAGES) ? slot + 2 - STAGES : slot + 2;
            LOADST1(ns, (t + 2) * BKW);
        }
        CP_COMMIT();

        const uint32_t* As = sm + slot * SW;
        const uint32_t* Bs = As + AW;

        uint32_t af[2][4][4];
        #pragma unroll
        for (int i = 0; i < 4; i++) {
            const int r0 = warpM * 64 + i * 16 + gid;
            af[0][i][0] = As[r0 * ASTRIDE + tg];
            af[0][i][1] = As[(r0 + 8) * ASTRIDE + tg];
            af[0][i][2] = As[r0 * ASTRIDE + tg + 4];
            af[0][i][3] = As[(r0 + 8) * ASTRIDE + tg + 4];
        }
        #pragma unroll
        for (int ks = 0; ks < 4; ks++) {
            const int cur = ks & 1, nxt = cur ^ 1;
            if (ks < 3) {
                const int cbw = (ks + 1) * 8;
                #pragma unroll
                for (int i = 0; i < 4; i++) {
                    const int r0 = warpM * 64 + i * 16 + gid;
                    af[nxt][i][0] = As[r0 * ASTRIDE + cbw + tg];
                    af[nxt][i][1] = As[(r0 + 8) * ASTRIDE + cbw + tg];
                    af[nxt][i][2] = As[r0 * ASTRIDE + cbw + tg + 4];
                    af[nxt][i][3] = As[(r0 + 8) * ASTRIDE + cbw + tg + 4];
                }
            }
            const int kp0 = ks * 8;
            #pragma unroll
            for (int j = 0; j < JN; j++) {
                const int col = warpN * (JN * 8) + j * 8 + gid;
                const uint32_t b0 = Bs[(kp0 + tg) * BSTRIDE + col];
                const uint32_t b1 = Bs[(kp0 + 4 + tg) * BSTRIDE + col];
                #pragma unroll
                for (int i = 0; i < 4; i++)
                    mma16(c[i][j], af[cur][i][0], af[cur][i][1],
                          af[cur][i][2], af[cur][i][3], b0, b1);
            }
        }
        slot = (slot + 1 >= STAGES) ? 0 : slot + 1;
    }
    #undef LOADST1

    #pragma unroll
    for (int i = 0; i < 4; i++) {
        const int r0 = bm + warpM * 64 + i * 16 + gid;
        #pragma unroll
        for (int j = 0; j < JN; j++) {
            const int n0 = bn + warpN * (JN * 8) + j * 8 + tg * 2;
            Yw[(size_t)r0 * (NPAD1 / 2) + (n0 >> 1)] =
                pkh2(c[i][j][0], c[i][j][1]);
            Yw[(size_t)(r0 + 8) * (NPAD1 / 2) + (n0 >> 1)] =
                pkh2(c[i][j][2], c[i][j][3]);
        }
    }
}

// 1-D grid, 896 CTAs: bids [0,768) full tiles, [768,896) edge tiles (last).
__global__ __launch_bounds__(NT, 2)
void gemm1(const uint32_t* __restrict__ Ag, const uint32_t* __restrict__ Bg,
           uint32_t* __restrict__ Yw) {
    const int bid = blockIdx.x;
    if (bid < 768) {
        gemm1_body<8>((bid / 6) * 128, (bid % 6) * 128, Ag, Bg, Yw);
    } else {
        gemm1_body<4>((bid - 768) * 128, 768, Ag, Bg, Yw);
    }
}

// ================================================================= GEMM 2
// Out = Yh[:, :832] @ B2 + alpha * Xh.  (R12-proven, unchanged.)
__global__ __launch_bounds__(NT, 2)
void gemm2(const uint32_t* __restrict__ Ag, const uint32_t* __restrict__ Bg,
           const uint32_t* __restrict__ Xh, const float* __restrict__ alphap,
           float* __restrict__ Out) {
    extern __shared__ __align__(128) uint32_t sm[];
    const int tid = threadIdx.x;
    const int lane = tid & 31, wid = tid >> 5;
    const int gid = lane >> 2, tg = lane & 3;
    const int warpM = wid >> 1, warpN = wid & 1;
    const int bm = blockIdx.y * 128, bn = blockIdx.x * 128;
    const uint32_t smu = s2u(sm);
    const float alpha = *alphap;
    constexpr int KT = KPAD / 64;                // 13

    float c[4][8][4];
    #pragma unroll
    for (int i = 0; i < 4; i++)
        #pragma unroll
        for (int j = 0; j < 8; j++)
            #pragma unroll
            for (int v = 0; v < 4; v++) c[i][j][v] = 0.0f;

    #define LOADST2(slot, kw0)                                                 \
    do {                                                                       \
        const uint32_t base = smu + (slot) * (SW * 4);                         \
        _Pragma("unroll")                                                      \
        for (int ii = 0; ii < 16; ii++) {                                      \
            const int id = tid + NT * ii;                                      \
            if (id < 1024) {                                                   \
                const int row = id >> 3, cc = id & 7;                          \
                cp16(base + (row * ASTRIDE + cc * 4) * 4,                      \
                     Ag + (size_t)(bm + row) * (NPAD1 / 2) + (kw0) + cc * 4);  \
            } else {                                                           \
                const int id2 = id - 1024;                                     \
                const int row = id2 >> 5, cc = id2 & 31;                       \
                cp16(base + (AW + row * BSTRIDE + cc * 4) * 4,                 \
                     Bg + (size_t)((kw0) + row) * D_DIM + bn + cc * 4);        \
            }                                                                  \
        }                                                                      \
    } while (0)

    LOADST2(0, 0);    CP_COMMIT();
    LOADST2(1, BKW);  CP_COMMIT();

    int slot = 0;
    for (int t = 0; t < KT; t++) {
        CP_WAIT1();
        __syncthreads();
        if (t + 2 < KT) {
            const int ns = (slot + 2 >= STAGES) ? slot + 2 - STAGES : slot + 2;
            LOADST2(ns, (t + 2) * BKW);
        }
        CP_COMMIT();

        const uint32_t* As = sm + slot * SW;
        const uint32_t* Bs = As + AW;

        uint32_t af[2][4][4];
        #pragma unroll
        for (int i = 0; i < 4; i++) {
            const int r0 = warpM * 64 + i * 16 + gid;
            af[0][i][0] = As[r0 * ASTRIDE + tg];
            af[0][i][1] = As[(r0 + 8) * ASTRIDE + tg];
            af[0][i][2] = As[r0 * ASTRIDE + tg + 4];
            af[0][i][3] = As[(r0 + 8) * ASTRIDE + tg + 4];
        }
        #pragma unroll
        for (int ks = 0; ks < 4; ks++) {
            const int cur = ks & 1, nxt = cur ^ 1;
            if (ks < 3) {
                const int cbw = (ks + 1) * 8;
                #pragma unroll
                for (int i = 0; i < 4; i++) {
                    const int r0 = warpM * 64 + i * 16 + gid;
                    af[nxt][i][0] = As[r0 * ASTRIDE + cbw + tg];
                    af[nxt][i][1] = As[(r0 + 8) * ASTRIDE + cbw + tg];
                    af[nxt][i][2] = As[r0 * ASTRIDE + cbw + tg + 4];
                    af[nxt][i][3] = As[(r0 + 8) * ASTRIDE + cbw + tg + 4];
                }
            }
            const int kp0 = ks * 8;
            #pragma unroll
            for (int j = 0; j < 8; j++) {
                const int col = warpN * 64 + j * 8 + gid;
                const uint32_t b0 = Bs[(kp0 + tg) * BSTRIDE + col];
                const uint32_t b1 = Bs[(kp0 + 4 + tg) * BSTRIDE + col];
                #pragma unroll
                for (int i = 0; i < 4; i++)
                    mma16(c[i][j], af[cur][i][0], af[cur][i][1],
                          af[cur][i][2], af[cur][i][3], b0, b1);
            }
        }
        slot = (slot + 1 >= STAGES) ? 0 : slot + 1;
    }
    #undef LOADST2

    #pragma unroll
    for (int i = 0; i < 4; i++) {
        const int r0 = bm + warpM * 64 + i * 16 + gid;
        #pragma unroll
        for (int j = 0; j < 8; j++) {
            const int n0 = bn + warpN * 64 + j * 8 + tg * 2;
            #pragma unroll
            for (int h = 0; h < 2; h++) {
                const size_t off = (size_t)(r0 + 8 * h) * D_DIM + n0;
                const uint32_t xw =
                    Xh[(size_t)(r0 + 8 * h) * (D_DIM / 2) + (n0 >> 1)];
                const float2 xv =
                    __half22float2(*reinterpret_cast<const __half2*>(&xw));
                float2 ov;
                ov.x = fmaf(alpha, xv.x, c[i][j][2 * h + 0]);
                ov.y = fmaf(alpha, xv.y, c[i][j][2 * h + 1]);
                *reinterpret_cast<float2*>(Out + off) = ov;
            }
        }
    }
}

// ---------------------------------------------------------------- launch
extern "C" void kernel_launch(void* const* d_in, const int* in_sizes, int n_in,
                              void* d_out, int out_size) {
    const float* x     = (const float*)d_in[0];
    const float* U     = (const float*)d_in[1];
    const float* S     = (const float*)d_in[2];
    const float* V     = (const float*)d_in[3];
    const float* alpha = (const float*)d_in[4];
    float* out = (float*)d_out;

    uint32_t *Xhp, *Yhp, *B1p, *B2p;
    cudaGetSymbolAddress((void**)&Xhp, g_Xh);
    cudaGetSymbolAddress((void**)&Yhp, g_Yh);
    cudaGetSymbolAddress((void**)&B1p, g_B1);
    cudaGetSymbolAddress((void**)&B2p, g_B2);

    cudaFuncSetAttribute(gemm1, cudaFuncAttributeMaxDynamicSharedMemorySize,
                         SMEM_B);
    cudaFuncSetAttribute(gemm2, cudaFuncAttributeMaxDynamicSharedMemorySize,
                         SMEM_B);

    prep_all<<<(unsigned)((NPREP + 255) / 256), 256>>>(
        (const float4*)x, (uint4*)Xhp, U, S, B1p, V, B2p);

    gemm1<<<896, NT, SMEM_B>>>(Xhp, B1p, Yhp);
    gemm2<<<dim3(D_DIM / 128, M_TOTAL / 128), NT, SMEM_B>>>(Yhp, B2p, Xhp,
                                                            alpha, out);
}